// round 4
// baseline (speedup 1.0000x reference)
#include <cuda_runtime.h>
#include <cuda_bf16.h>
#include <cstdint>

// Problem: tensor [8192, 64, 64] fp32.
// Per batch b: (mx,my) = 2D coords of argmax (first occurrence).
// loss = sum_b sum_{j,k} ((mx-j)^2 + (my-k)^2) * t[b,j,k]
// Decompose: = (mx^2+my^2)*S - 2*mx*Sj + Sjj - 2*my*Sk + Skk
// with moments S,Sj,Sjj,Sk,Skk independent of the argmax -> single pass.

#define NB 8192
#define HH 64
#define WW 64
#define HW (HH*WW)          // 4096
#define THREADS 256
#define NWARPS (THREADS/32)

__device__ float g_batch_loss[NB];

__global__ __launch_bounds__(THREADS, 8)
void per_batch_kernel(const float* __restrict__ in) {
    const int b = blockIdx.x;
    const float4* __restrict__ p =
        reinterpret_cast<const float4*>(in + (size_t)b * HW);
    const int t = threadIdx.x;

    float s = 0.f, sj = 0.f, sjj = 0.f, sk = 0.f, skk = 0.f;
    float best = -1.0f;        // inputs are uniform [0,1)
    int bestIdx = 0;

    // 4096 floats = 1024 float4; 256 threads x 4 iterations, coalesced.
    #pragma unroll
    for (int it = 0; it < 4; ++it) {
        const int i = t + it * THREADS;     // float4 index
        const float4 v = p[i];
        const int flat = i << 2;            // element index of v.x
        const float j  = (float)(flat >> 6);
        const float k0 = (float)(flat & 63);
        const float k1 = k0 + 1.0f, k2 = k0 + 2.0f, k3 = k0 + 3.0f;

        const float rs = (v.x + v.y) + (v.z + v.w);
        s   += rs;
        sj  += j * rs;
        sjj += (j * j) * rs;
        sk  += k0 * v.x + k1 * v.y + k2 * v.z + k3 * v.w;
        skk += (k0 * k0) * v.x + (k1 * k1) * v.y
             + (k2 * k2) * v.z + (k3 * k3) * v.w;

        // strict > in ascending flat order keeps first occurrence
        if (v.x > best) { best = v.x; bestIdx = flat;     }
        if (v.y > best) { best = v.y; bestIdx = flat + 1; }
        if (v.z > best) { best = v.z; bestIdx = flat + 2; }
        if (v.w > best) { best = v.w; bestIdx = flat + 3; }
    }

    // ---- warp reduction ----
    const unsigned FULL = 0xFFFFFFFFu;
    #pragma unroll
    for (int off = 16; off > 0; off >>= 1) {
        float ov = __shfl_down_sync(FULL, best, off);
        int   oi = __shfl_down_sync(FULL, bestIdx, off);
        if (ov > best || (ov == best && oi < bestIdx)) { best = ov; bestIdx = oi; }
        s   += __shfl_down_sync(FULL, s,   off);
        sj  += __shfl_down_sync(FULL, sj,  off);
        sjj += __shfl_down_sync(FULL, sjj, off);
        sk  += __shfl_down_sync(FULL, sk,  off);
        skk += __shfl_down_sync(FULL, skk, off);
    }

    // ---- cross-warp reduction via shared ----
    __shared__ float sh_s[NWARPS], sh_sj[NWARPS], sh_sjj[NWARPS],
                     sh_sk[NWARPS], sh_skk[NWARPS], sh_mv[NWARPS];
    __shared__ int   sh_mi[NWARPS];
    const int warp = t >> 5, lane = t & 31;
    if (lane == 0) {
        sh_s[warp] = s;   sh_sj[warp] = sj;  sh_sjj[warp] = sjj;
        sh_sk[warp] = sk; sh_skk[warp] = skk;
        sh_mv[warp] = best; sh_mi[warp] = bestIdx;
    }
    __syncthreads();

    if (t == 0) {
        float S = sh_s[0], SJ = sh_sj[0], SJJ = sh_sjj[0],
              SK = sh_sk[0], SKK = sh_skk[0];
        float MV = sh_mv[0]; int MI = sh_mi[0];
        #pragma unroll
        for (int w = 1; w < NWARPS; ++w) {
            S += sh_s[w]; SJ += sh_sj[w]; SJJ += sh_sjj[w];
            SK += sh_sk[w]; SKK += sh_skk[w];
            if (sh_mv[w] > MV || (sh_mv[w] == MV && sh_mi[w] < MI)) {
                MV = sh_mv[w]; MI = sh_mi[w];
            }
        }
        const float mx = (float)(MI >> 6);
        const float my = (float)(MI & 63);
        const float loss = (mx * mx + my * my) * S
                         - 2.0f * mx * SJ + SJJ
                         - 2.0f * my * SK + SKK;
        g_batch_loss[b] = loss;
    }
}

__global__ void reduce_kernel(float* __restrict__ out) {
    __shared__ float sm[1024];
    const int t = threadIdx.x;
    float s = 0.f;
    #pragma unroll
    for (int i = 0; i < NB / 1024; ++i)
        s += g_batch_loss[t + i * 1024];
    sm[t] = s;
    __syncthreads();
    #pragma unroll
    for (int o = 512; o > 0; o >>= 1) {
        if (t < o) sm[t] += sm[t + o];
        __syncthreads();
    }
    if (t == 0) out[0] = sm[0];
}

extern "C" void kernel_launch(void* const* d_in, const int* in_sizes, int n_in,
                              void* d_out, int out_size) {
    const float* in = (const float*)d_in[0];
    float* out = (float*)d_out;
    per_batch_kernel<<<NB, THREADS>>>(in);
    reduce_kernel<<<1, 1024>>>(out);
}